// round 2
// baseline (speedup 1.0000x reference)
#include <cuda_runtime.h>
#include <cuda_bf16.h>
#include <math.h>

// ---------------------------------------------------------------------------
// GatingMixedDecoder: gate MLP -> softmax coeff -> 5 soft-mixed expert layers.
// mix(coeff,x,w) folded into a single GEMM with K = E*d1 and A-load scaled by
// coeff[b, k/d1].  All fp32.
// ---------------------------------------------------------------------------

#define Bsz    4096
#define LATENT 768
#define COND   512
#define HIDDEN 1024
#define OUTD   512
#define NEXP   8
#define GATE_H 512
#define INPUTD 1280   // LATENT+COND
#define INTERD 1792   // LATENT+HIDDEN
#define NEG_SLOPE 0.01f
#define LN_EPS 1e-5f

// scratch (device globals; no allocation allowed)
__device__ float g_h1[Bsz * GATE_H];
__device__ float g_h2[Bsz * GATE_H];
__device__ float g_coeff[Bsz * NEXP];
__device__ float g_xn[Bsz * INTERD];
__device__ float g_lo[Bsz * HIDDEN];
__device__ float g_mixb[Bsz * HIDDEN];

// ---------------------------------------------------------------------------
// SGEMM: C[M,N] = A[M,K] @ B[K,N] (+ epilogue)
// BM=128 BN=128 BK=8, 256 threads, 8x8 per-thread tile.
// AMODE: 0 = plain A1[M,K]
//        1 = concat(A1=z [M,768], A2 [M,K-768])
//        2 = MoE: A1 = x[M,d1], coeff[M,8], K = 8*d1, A = coeff[b,k/d1]*x[b,k%d1]
// EPI:   0 = + addend[n] (bias), leaky
//        1 = + addend[b,n] (mixed bias), leaky
//        2 = + addend[b,n] + resid[b,n], leaky
//        3 = + addend[b,n], no activation
// ---------------------------------------------------------------------------
template <int AMODE, int EPI>
__global__ void __launch_bounds__(256)
sgemm_kernel(const float* __restrict__ A1, const float* __restrict__ A2,
             const float* __restrict__ coeff, const float* __restrict__ Bw,
             const float* __restrict__ addend, const float* __restrict__ resid,
             float* __restrict__ C, int M, int N, int K, int d1)
{
    const int BM = 128, BN = 128, BK = 8;
    __shared__ float As[BK][BM];
    __shared__ float Bs[BK][BN];

    const int tid = threadIdx.x;
    const int bm = blockIdx.y * BM;
    const int bn = blockIdx.x * BN;

    const int tx = tid & 15;   // column group (0..15)
    const int ty = tid >> 4;   // row group    (0..15)

    // A load: thread -> (row tid>>1, col 4*(tid&1))
    const int a_r = tid >> 1;
    const int a_c = (tid & 1) * 4;
    // B load: thread -> (row tid>>5, col 4*(tid&31))
    const int b_r = tid >> 5;
    const int b_c = (tid & 31) * 4;

    float acc[8][8];
#pragma unroll
    for (int r = 0; r < 8; r++)
#pragma unroll
        for (int cc = 0; cc < 8; cc++) acc[r][cc] = 0.f;

    for (int k0 = 0; k0 < K; k0 += BK) {
        // ---- load A tile (128x8) ----
        const int gm = bm + a_r;
        const int gk = k0 + a_c;
        float4 av;
        if (AMODE == 0) {
            av = *reinterpret_cast<const float4*>(A1 + (size_t)gm * K + gk);
        } else if (AMODE == 1) {
            if (gk < LATENT)
                av = *reinterpret_cast<const float4*>(A1 + (size_t)gm * LATENT + gk);
            else
                av = *reinterpret_cast<const float4*>(A2 + (size_t)gm * (K - LATENT) + (gk - LATENT));
        } else {
            const int e = gk / d1;           // constant across the 4 elems (d1 % 8 == 0)
            const int j = gk - e * d1;
            const float cf = __ldg(coeff + gm * NEXP + e);
            float4 x = *reinterpret_cast<const float4*>(A1 + (size_t)gm * d1 + j);
            av = make_float4(x.x * cf, x.y * cf, x.z * cf, x.w * cf);
        }
        As[a_c + 0][a_r] = av.x;
        As[a_c + 1][a_r] = av.y;
        As[a_c + 2][a_r] = av.z;
        As[a_c + 3][a_r] = av.w;

        // ---- load B tile (8x128) ----
        *reinterpret_cast<float4*>(&Bs[b_r][b_c]) =
            *reinterpret_cast<const float4*>(Bw + (size_t)(k0 + b_r) * N + bn + b_c);

        __syncthreads();

#pragma unroll
        for (int kk = 0; kk < BK; kk++) {
            float4 a0 = *reinterpret_cast<const float4*>(&As[kk][ty * 4]);
            float4 a1 = *reinterpret_cast<const float4*>(&As[kk][64 + ty * 4]);
            float4 b0 = *reinterpret_cast<const float4*>(&Bs[kk][tx * 4]);
            float4 b1 = *reinterpret_cast<const float4*>(&Bs[kk][64 + tx * 4]);
            float ar[8] = {a0.x, a0.y, a0.z, a0.w, a1.x, a1.y, a1.z, a1.w};
            float br[8] = {b0.x, b0.y, b0.z, b0.w, b1.x, b1.y, b1.z, b1.w};
#pragma unroll
            for (int r = 0; r < 8; r++)
#pragma unroll
                for (int cc = 0; cc < 8; cc++) acc[r][cc] = fmaf(ar[r], br[cc], acc[r][cc]);
        }
        __syncthreads();
    }

    // ---- epilogue ----
#pragma unroll
    for (int r = 0; r < 8; r++) {
        const int gr = bm + ((r < 4) ? (ty * 4 + r) : (64 + ty * 4 + r - 4));
#pragma unroll
        for (int cc = 0; cc < 8; cc++) {
            const int gc = bn + ((cc < 4) ? (tx * 4 + cc) : (64 + tx * 4 + cc - 4));
            float v = acc[r][cc];
            if (EPI == 0) v += addend[gc];
            else          v += addend[(size_t)gr * N + gc];
            if (EPI == 2) v += resid[(size_t)gr * N + gc];
            if (EPI != 3) v = (v > 0.f) ? v : NEG_SLOPE * v;
            C[(size_t)gr * N + gc] = v;
        }
    }
}

// ---------------------------------------------------------------------------
// LayerNorm over concat(z[768], src[srclen]) -> out[M, d], d = 768+srclen
// one block per row
// ---------------------------------------------------------------------------
__global__ void __launch_bounds__(256)
ln_kernel(const float* __restrict__ z, const float* __restrict__ src, int srclen,
          const float* __restrict__ g, const float* __restrict__ b,
          float* __restrict__ out, int d)
{
    const int row = blockIdx.x;
    __shared__ float buf[INTERD];
    __shared__ float red[256];
    const int tid = threadIdx.x;

    float s = 0.f;
    for (int j = tid; j < d; j += 256) {
        float v = (j < LATENT) ? z[(size_t)row * LATENT + j]
                               : src[(size_t)row * srclen + (j - LATENT)];
        buf[j] = v;
        s += v;
    }
    red[tid] = s; __syncthreads();
    for (int o = 128; o > 0; o >>= 1) { if (tid < o) red[tid] += red[tid + o]; __syncthreads(); }
    const float mu = red[0] / d;
    __syncthreads();

    float sq = 0.f;
    for (int j = tid; j < d; j += 256) { float t = buf[j] - mu; sq += t * t; }
    red[tid] = sq; __syncthreads();
    for (int o = 128; o > 0; o >>= 1) { if (tid < o) red[tid] += red[tid + o]; __syncthreads(); }
    const float rstd = rsqrtf(red[0] / d + LN_EPS);
    __syncthreads();

    for (int j = tid; j < d; j += 256)
        out[(size_t)row * d + j] = (buf[j] - mu) * rstd * g[j] + b[j];
}

// ---------------------------------------------------------------------------
// gate layer 3: logits = h[4096,512] @ W[512,8] + bias; coeff = softmax(logits)
// one warp per row
// ---------------------------------------------------------------------------
__global__ void __launch_bounds__(256)
gate2_kernel(const float* __restrict__ h, const float* __restrict__ W,
             const float* __restrict__ bias, float* __restrict__ coeff)
{
    const int warp = (blockIdx.x * blockDim.x + threadIdx.x) >> 5;
    const int lane = threadIdx.x & 31;
    if (warp >= Bsz) return;

    float acc[NEXP];
#pragma unroll
    for (int e = 0; e < NEXP; e++) acc[e] = 0.f;

    for (int j = lane; j < GATE_H; j += 32) {
        const float hv = h[(size_t)warp * GATE_H + j];
        const float4 w0 = *reinterpret_cast<const float4*>(W + (size_t)j * NEXP);
        const float4 w1 = *reinterpret_cast<const float4*>(W + (size_t)j * NEXP + 4);
        acc[0] = fmaf(hv, w0.x, acc[0]); acc[1] = fmaf(hv, w0.y, acc[1]);
        acc[2] = fmaf(hv, w0.z, acc[2]); acc[3] = fmaf(hv, w0.w, acc[3]);
        acc[4] = fmaf(hv, w1.x, acc[4]); acc[5] = fmaf(hv, w1.y, acc[5]);
        acc[6] = fmaf(hv, w1.z, acc[6]); acc[7] = fmaf(hv, w1.w, acc[7]);
    }
#pragma unroll
    for (int e = 0; e < NEXP; e++)
#pragma unroll
        for (int o = 16; o > 0; o >>= 1)
            acc[e] += __shfl_down_sync(0xffffffffu, acc[e], o);

    if (lane == 0) {
        float v[NEXP], m = -1e30f;
#pragma unroll
        for (int e = 0; e < NEXP; e++) { v[e] = acc[e] + bias[e]; m = fmaxf(m, v[e]); }
        float s = 0.f;
#pragma unroll
        for (int e = 0; e < NEXP; e++) { v[e] = __expf(v[e] - m); s += v[e]; }
        const float inv = 1.f / s;
#pragma unroll
        for (int e = 0; e < NEXP; e++) coeff[(size_t)warp * NEXP + e] = v[e] * inv;
    }
}

// ---------------------------------------------------------------------------
// mixed bias: mixb[b,n] = sum_e coeff[b,e] * bias[e,n]
// ---------------------------------------------------------------------------
__global__ void __launch_bounds__(256)
mixbias_kernel(const float* __restrict__ coeff, const float* __restrict__ bias,
               float* __restrict__ out, int N)
{
    const int idx = blockIdx.x * blockDim.x + threadIdx.x;
    if (idx >= Bsz * N) return;
    const int b = idx / N, n = idx - b * N;
    const float* cf = coeff + (size_t)b * NEXP;
    float s = 0.f;
#pragma unroll
    for (int e = 0; e < NEXP; e++) s = fmaf(cf[e], bias[(size_t)e * N + n], s);
    out[idx] = s;
}

// ---------------------------------------------------------------------------
extern "C" void kernel_launch(void* const* d_in, const int* in_sizes, int n_in,
                              void* d_out, int out_size)
{
    const float* z = (const float*)d_in[0];
    const float* c = (const float*)d_in[1];
    const float *w[5], *bb[5], *lng[5], *lnb[5], *gW[3], *gbv[3];

    // input ordering: dict-insertion order (w,b,ln_g,ln_b interleaved) vs
    // signature order (all w/b then all ln). Distinguish by in_sizes[4].
    const bool dict_order = (in_sizes[4] == INPUTD);
    if (dict_order) {
        for (int i = 0; i < 5; i++) {
            w[i]   = (const float*)d_in[2 + 4 * i];
            bb[i]  = (const float*)d_in[3 + 4 * i];
            lng[i] = (const float*)d_in[4 + 4 * i];
            lnb[i] = (const float*)d_in[5 + 4 * i];
        }
    } else {
        for (int i = 0; i < 5; i++) {
            w[i]   = (const float*)d_in[2 + 2 * i];
            bb[i]  = (const float*)d_in[3 + 2 * i];
            lng[i] = (const float*)d_in[12 + 2 * i];
            lnb[i] = (const float*)d_in[13 + 2 * i];
        }
    }
    for (int j = 0; j < 3; j++) {
        gW[j]  = (const float*)d_in[22 + 2 * j];
        gbv[j] = (const float*)d_in[23 + 2 * j];
    }

    float *h1, *h2, *coeff, *xn, *lo, *mixb;
    cudaGetSymbolAddress((void**)&h1,    g_h1);
    cudaGetSymbolAddress((void**)&h2,    g_h2);
    cudaGetSymbolAddress((void**)&coeff, g_coeff);
    cudaGetSymbolAddress((void**)&xn,    g_xn);
    cudaGetSymbolAddress((void**)&lo,    g_lo);
    cudaGetSymbolAddress((void**)&mixb,  g_mixb);

    // ---- gate MLP ----
    sgemm_kernel<1, 0><<<dim3(GATE_H / 128, Bsz / 128), 256>>>(
        z, c, nullptr, gW[0], gbv[0], nullptr, h1, Bsz, GATE_H, INPUTD, 0);
    sgemm_kernel<0, 0><<<dim3(GATE_H / 128, Bsz / 128), 256>>>(
        h1, nullptr, nullptr, gW[1], gbv[1], nullptr, h2, Bsz, GATE_H, GATE_H, 0);
    gate2_kernel<<<(Bsz * 32 + 255) / 256, 256>>>(h2, gW[2], gbv[2], coeff);

    // ---- layer 0 ----
    ln_kernel<<<Bsz, 256>>>(z, c, COND, lng[0], lnb[0], xn, INPUTD);
    mixbias_kernel<<<(Bsz * HIDDEN + 255) / 256, 256>>>(coeff, bb[0], mixb, HIDDEN);
    sgemm_kernel<2, 1><<<dim3(HIDDEN / 128, Bsz / 128), 256>>>(
        xn, nullptr, coeff, w[0], mixb, nullptr, lo, Bsz, HIDDEN, NEXP * INPUTD, INPUTD);

    // ---- layers 1..3 (residual) ----
    for (int i = 1; i <= 3; i++) {
        ln_kernel<<<Bsz, 256>>>(z, lo, HIDDEN, lng[i], lnb[i], xn, INTERD);
        mixbias_kernel<<<(Bsz * HIDDEN + 255) / 256, 256>>>(coeff, bb[i], mixb, HIDDEN);
        sgemm_kernel<2, 2><<<dim3(HIDDEN / 128, Bsz / 128), 256>>>(
            xn, nullptr, coeff, w[i], mixb, lo, lo, Bsz, HIDDEN, NEXP * INTERD, INTERD);
    }

    // ---- final layer ----
    ln_kernel<<<Bsz, 256>>>(z, lo, HIDDEN, lng[4], lnb[4], xn, INTERD);
    mixbias_kernel<<<(Bsz * OUTD + 255) / 256, 256>>>(coeff, bb[4], mixb, OUTD);
    sgemm_kernel<2, 3><<<dim3(OUTD / 128, Bsz / 128), 256>>>(
        xn, nullptr, coeff, w[4], mixb, nullptr, (float*)d_out, Bsz, OUTD, NEXP * INTERD, INTERD);
}

// round 4
// speedup vs baseline: 1.7143x; 1.7143x over previous
#include <cuda_runtime.h>
#include <cuda_bf16.h>
#include <math.h>

// ---------------------------------------------------------------------------
// GatingMixedDecoder: gate MLP -> softmax coeff -> 5 soft-mixed expert layers.
// mix(coeff,x,w) folded into one GEMM with K = E*d1, A scaled by coeff[b,k/d1].
// GEMMs on tf32 tensor cores (mma.sync m16n8k8), fp32 epilogues.
// ---------------------------------------------------------------------------

#define Bsz    4096
#define LATENT 768
#define COND   512
#define HIDDEN 1024
#define OUTD   512
#define NEXP   8
#define GATE_H 512
#define INPUTD 1280   // LATENT+COND
#define INTERD 1792   // LATENT+HIDDEN
#define NEG_SLOPE 0.01f
#define LN_EPS 1e-5f

// scratch (device globals; no allocation allowed)
__device__ float g_h1[Bsz * GATE_H];
__device__ float g_h2[Bsz * GATE_H];
__device__ float g_coeff[Bsz * NEXP];
__device__ float g_xn[Bsz * INTERD];
__device__ float g_lo[Bsz * HIDDEN];
__device__ float g_mixb[Bsz * HIDDEN];

__device__ __forceinline__ unsigned f2tf32(float f) {
    unsigned u;
    asm("cvt.rna.tf32.f32 %0, %1;" : "=r"(u) : "f"(f));
    return u;
}

// ---------------------------------------------------------------------------
// tf32 tensor-core GEMM: C[M,N] = A[M,K] @ B[K,N] (+ epilogue)
// BM=128 BN=128 BK=16, 256 threads (8 warps), warp tile 64x32 (m16n8k8 frags).
// AMODE: 0 = plain A1[M,K]
//        1 = concat(A1=z [M,768], A2 [M,K-768])
//        2 = MoE: A1 = x[M,d1], coeff[M,8], K = 8*d1, A = coeff[b,k/d1]*x[b,j]
// EPI:   0 = + addend[n] (bias), leaky
//        1 = + addend[b,n] (mixed bias), leaky
//        2 = + addend[b,n] + resid[b,n], leaky
//        3 = + addend[b,n], no activation
// Requires M%128==0, N%128==0, K%16==0 (true for all call sites).
// ---------------------------------------------------------------------------
template <int AMODE, int EPI>
__global__ void __launch_bounds__(256)
tf32gemm_kernel(const float* __restrict__ A1, const float* __restrict__ A2,
                const float* __restrict__ coeff, const float* __restrict__ Bw,
                const float* __restrict__ addend, const float* __restrict__ resid,
                float* __restrict__ C, int M, int N, int K, int d1)
{
    const int BM = 128, BN = 128, BK = 16;
    // padded for conflict-free fragment loads:
    //  As stride 20: (m*20 + k) % 32 distinct over m=lane>>2 (8 vals), k=lane&3
    //  Bs stride 136: (k*136 + n) % 32 = k*8 + n distinct over k=lane&3, n=lane>>2
    __shared__ float As[BM][20];
    __shared__ float Bs[BK][136];

    const int tid  = threadIdx.x;
    const int warp = tid >> 5;
    const int lane = tid & 31;
    const int warp_m = (warp >> 2) * 64;   // 0..1 -> 0,64
    const int warp_n = (warp & 3) * 32;    // 0..3 -> 0,32,64,96
    const int grp = lane >> 2;             // 0..7
    const int tig = lane & 3;              // 0..3

    const int bm = blockIdx.y * BM;
    const int bn = blockIdx.x * BN;

    float acc[4][4][4];
#pragma unroll
    for (int i = 0; i < 4; i++)
#pragma unroll
        for (int j = 0; j < 4; j++)
#pragma unroll
            for (int r = 0; r < 4; r++) acc[i][j][r] = 0.f;

    // gmem staging registers (software pipeline)
    float4 a_reg[2], b_reg[2];

    // A: 512 float4 per tile -> 2 per thread. idx = tid + i*256
    //    row = idx>>2 (0..127), col = (idx&3)*4
    // B: idx -> row = idx>>5 (0..15), col = (idx&31)*4
#define LOAD_TILE(k0)                                                           \
    {                                                                           \
        _Pragma("unroll")                                                       \
        for (int i = 0; i < 2; i++) {                                           \
            const int idx = tid + i * 256;                                      \
            const int ar = idx >> 2, ac = (idx & 3) * 4;                        \
            const int gm = bm + ar, gk = (k0) + ac;                             \
            if (AMODE == 0) {                                                   \
                a_reg[i] = *reinterpret_cast<const float4*>(A1 + (size_t)gm * K + gk); \
            } else if (AMODE == 1) {                                            \
                if (gk < LATENT)                                                \
                    a_reg[i] = *reinterpret_cast<const float4*>(A1 + (size_t)gm * LATENT + gk); \
                else                                                            \
                    a_reg[i] = *reinterpret_cast<const float4*>(A2 + (size_t)gm * (K - LATENT) + (gk - LATENT)); \
            } else {                                                            \
                const int e = gk / d1;                                          \
                const int j = gk - e * d1;                                      \
                const float cf = __ldg(coeff + gm * NEXP + e);                  \
                float4 x = *reinterpret_cast<const float4*>(A1 + (size_t)gm * d1 + j); \
                a_reg[i] = make_float4(x.x * cf, x.y * cf, x.z * cf, x.w * cf); \
            }                                                                   \
            const int br = idx >> 5, bc = (idx & 31) * 4;                       \
            b_reg[i] = *reinterpret_cast<const float4*>(Bw + (size_t)((k0) + br) * N + bn + bc); \
        }                                                                       \
    }

#define STORE_TILE()                                                            \
    {                                                                           \
        _Pragma("unroll")                                                       \
        for (int i = 0; i < 2; i++) {                                           \
            const int idx = tid + i * 256;                                      \
            const int ar = idx >> 2, ac = (idx & 3) * 4;                        \
            As[ar][ac + 0] = __uint_as_float(f2tf32(a_reg[i].x));               \
            As[ar][ac + 1] = __uint_as_float(f2tf32(a_reg[i].y));               \
            As[ar][ac + 2] = __uint_as_float(f2tf32(a_reg[i].z));               \
            As[ar][ac + 3] = __uint_as_float(f2tf32(a_reg[i].w));               \
            const int br = idx >> 5, bc = (idx & 31) * 4;                       \
            Bs[br][bc + 0] = __uint_as_float(f2tf32(b_reg[i].x));               \
            Bs[br][bc + 1] = __uint_as_float(f2tf32(b_reg[i].y));               \
            Bs[br][bc + 2] = __uint_as_float(f2tf32(b_reg[i].z));               \
            Bs[br][bc + 3] = __uint_as_float(f2tf32(b_reg[i].w));               \
        }                                                                       \
    }

    LOAD_TILE(0);

    for (int k0 = 0; k0 < K; k0 += BK) {
        __syncthreads();
        STORE_TILE();
        __syncthreads();
        if (k0 + BK < K) LOAD_TILE(k0 + BK);

#pragma unroll
        for (int ks = 0; ks < 2; ks++) {
            const int kk = ks * 8;
            // B fragments: 4 n-tiles x 2 regs
            unsigned bfr[4][2];
#pragma unroll
            for (int nt = 0; nt < 4; nt++) {
                const int n = warp_n + nt * 8 + grp;
                bfr[nt][0] = __float_as_uint(Bs[kk + tig][n]);
                bfr[nt][1] = __float_as_uint(Bs[kk + 4 + tig][n]);
            }
            // A fragments: 4 m-tiles x 4 regs
            unsigned afr[4][4];
#pragma unroll
            for (int mt = 0; mt < 4; mt++) {
                const int m = warp_m + mt * 16 + grp;
                afr[mt][0] = __float_as_uint(As[m][kk + tig]);
                afr[mt][1] = __float_as_uint(As[m + 8][kk + tig]);
                afr[mt][2] = __float_as_uint(As[m][kk + 4 + tig]);
                afr[mt][3] = __float_as_uint(As[m + 8][kk + 4 + tig]);
            }
#pragma unroll
            for (int mt = 0; mt < 4; mt++)
#pragma unroll
                for (int nt = 0; nt < 4; nt++) {
                    asm volatile(
                        "mma.sync.aligned.m16n8k8.row.col.f32.tf32.tf32.f32 "
                        "{%0,%1,%2,%3}, {%4,%5,%6,%7}, {%8,%9}, {%0,%1,%2,%3};"
                        : "+f"(acc[mt][nt][0]), "+f"(acc[mt][nt][1]),
                          "+f"(acc[mt][nt][2]), "+f"(acc[mt][nt][3])
                        : "r"(afr[mt][0]), "r"(afr[mt][1]),
                          "r"(afr[mt][2]), "r"(afr[mt][3]),
                          "r"(bfr[nt][0]), "r"(bfr[nt][1]));
                }
        }
    }

    // ---- epilogue: c0,c1 at (row, col..col+1); c2,c3 at (row+8, col..col+1) ----
#pragma unroll
    for (int mt = 0; mt < 4; mt++) {
        const int r0 = bm + warp_m + mt * 16 + grp;
#pragma unroll
        for (int nt = 0; nt < 4; nt++) {
            const int c0 = bn + warp_n + nt * 8 + tig * 2;
#pragma unroll
            for (int half = 0; half < 2; half++) {
                const int gr = r0 + half * 8;
                float v0 = acc[mt][nt][half * 2 + 0];
                float v1 = acc[mt][nt][half * 2 + 1];
                if (EPI == 0) {
                    const float2 ad = *reinterpret_cast<const float2*>(addend + c0);
                    v0 += ad.x; v1 += ad.y;
                } else {
                    const float2 ad = *reinterpret_cast<const float2*>(addend + (size_t)gr * N + c0);
                    v0 += ad.x; v1 += ad.y;
                }
                if (EPI == 2) {
                    const float2 rs = *reinterpret_cast<const float2*>(resid + (size_t)gr * N + c0);
                    v0 += rs.x; v1 += rs.y;
                }
                if (EPI != 3) {
                    v0 = (v0 > 0.f) ? v0 : NEG_SLOPE * v0;
                    v1 = (v1 > 0.f) ? v1 : NEG_SLOPE * v1;
                }
                *reinterpret_cast<float2*>(C + (size_t)gr * N + c0) = make_float2(v0, v1);
            }
        }
    }
#undef LOAD_TILE
#undef STORE_TILE
}

// ---------------------------------------------------------------------------
// LayerNorm over concat(z[768], src[srclen]) -> out[M, d], d = 768+srclen
// ---------------------------------------------------------------------------
__global__ void __launch_bounds__(256)
ln_kernel(const float* __restrict__ z, const float* __restrict__ src, int srclen,
          const float* __restrict__ g, const float* __restrict__ b,
          float* __restrict__ out, int d)
{
    const int row = blockIdx.x;
    __shared__ float buf[INTERD];
    __shared__ float red[256];
    const int tid = threadIdx.x;

    float s = 0.f;
    for (int j = tid; j < d; j += 256) {
        float v = (j < LATENT) ? z[(size_t)row * LATENT + j]
                               : src[(size_t)row * srclen + (j - LATENT)];
        buf[j] = v;
        s += v;
    }
    red[tid] = s; __syncthreads();
    for (int o = 128; o > 0; o >>= 1) { if (tid < o) red[tid] += red[tid + o]; __syncthreads(); }
    const float mu = red[0] / d;
    __syncthreads();

    float sq = 0.f;
    for (int j = tid; j < d; j += 256) { float t = buf[j] - mu; sq += t * t; }
    red[tid] = sq; __syncthreads();
    for (int o = 128; o > 0; o >>= 1) { if (tid < o) red[tid] += red[tid + o]; __syncthreads(); }
    const float rstd = rsqrtf(red[0] / d + LN_EPS);
    __syncthreads();

    for (int j = tid; j < d; j += 256)
        out[(size_t)row * d + j] = (buf[j] - mu) * rstd * g[j] + b[j];
}

// ---------------------------------------------------------------------------
// gate layer 3: logits = h[4096,512] @ W[512,8] + bias; coeff = softmax(logits)
// ---------------------------------------------------------------------------
__global__ void __launch_bounds__(256)
gate2_kernel(const float* __restrict__ h, const float* __restrict__ W,
             const float* __restrict__ bias, float* __restrict__ coeff)
{
    const int warp = (blockIdx.x * blockDim.x + threadIdx.x) >> 5;
    const int lane = threadIdx.x & 31;
    if (warp >= Bsz) return;

    float acc[NEXP];
#pragma unroll
    for (int e = 0; e < NEXP; e++) acc[e] = 0.f;

    for (int j = lane; j < GATE_H; j += 32) {
        const float hv = h[(size_t)warp * GATE_H + j];
        const float4 w0 = *reinterpret_cast<const float4*>(W + (size_t)j * NEXP);
        const float4 w1 = *reinterpret_cast<const float4*>(W + (size_t)j * NEXP + 4);
        acc[0] = fmaf(hv, w0.x, acc[0]); acc[1] = fmaf(hv, w0.y, acc[1]);
        acc[2] = fmaf(hv, w0.z, acc[2]); acc[3] = fmaf(hv, w0.w, acc[3]);
        acc[4] = fmaf(hv, w1.x, acc[4]); acc[5] = fmaf(hv, w1.y, acc[5]);
        acc[6] = fmaf(hv, w1.z, acc[6]); acc[7] = fmaf(hv, w1.w, acc[7]);
    }
#pragma unroll
    for (int e = 0; e < NEXP; e++)
#pragma unroll
        for (int o = 16; o > 0; o >>= 1)
            acc[e] += __shfl_down_sync(0xffffffffu, acc[e], o);

    if (lane == 0) {
        float v[NEXP], m = -1e30f;
#pragma unroll
        for (int e = 0; e < NEXP; e++) { v[e] = acc[e] + bias[e]; m = fmaxf(m, v[e]); }
        float s = 0.f;
#pragma unroll
        for (int e = 0; e < NEXP; e++) { v[e] = __expf(v[e] - m); s += v[e]; }
        const float inv = 1.f / s;
#pragma unroll
        for (int e = 0; e < NEXP; e++) coeff[(size_t)warp * NEXP + e] = v[e] * inv;
    }
}

// ---------------------------------------------------------------------------
// mixed bias: mixb[b,n] = sum_e coeff[b,e] * bias[e,n]
// ---------------------------------------------------------------------------
__global__ void __launch_bounds__(256)
mixbias_kernel(const float* __restrict__ coeff, const float* __restrict__ bias,
               float* __restrict__ out, int N)
{
    const int idx = blockIdx.x * blockDim.x + threadIdx.x;
    if (idx >= Bsz * N) return;
    const int b = idx / N, n = idx - b * N;
    const float* cf = coeff + (size_t)b * NEXP;
    float s = 0.f;
#pragma unroll
    for (int e = 0; e < NEXP; e++) s = fmaf(cf[e], bias[(size_t)e * N + n], s);
    out[idx] = s;
}

// ---------------------------------------------------------------------------
extern "C" void kernel_launch(void* const* d_in, const int* in_sizes, int n_in,
                              void* d_out, int out_size)
{
    const float* z = (const float*)d_in[0];
    const float* c = (const float*)d_in[1];
    const float *w[5], *bb[5], *lng[5], *lnb[5], *gW[3], *gbv[3];

    const bool dict_order = (in_sizes[4] == INPUTD);
    if (dict_order) {
        for (int i = 0; i < 5; i++) {
            w[i]   = (const float*)d_in[2 + 4 * i];
            bb[i]  = (const float*)d_in[3 + 4 * i];
            lng[i] = (const float*)d_in[4 + 4 * i];
            lnb[i] = (const float*)d_in[5 + 4 * i];
        }
    } else {
        for (int i = 0; i < 5; i++) {
            w[i]   = (const float*)d_in[2 + 2 * i];
            bb[i]  = (const float*)d_in[3 + 2 * i];
            lng[i] = (const float*)d_in[12 + 2 * i];
            lnb[i] = (const float*)d_in[13 + 2 * i];
        }
    }
    for (int j = 0; j < 3; j++) {
        gW[j]  = (const float*)d_in[22 + 2 * j];
        gbv[j] = (const float*)d_in[23 + 2 * j];
    }

    float *h1, *h2, *coeff, *xn, *lo, *mixb;
    cudaGetSymbolAddress((void**)&h1,    g_h1);
    cudaGetSymbolAddress((void**)&h2,    g_h2);
    cudaGetSymbolAddress((void**)&coeff, g_coeff);
    cudaGetSymbolAddress((void**)&xn,    g_xn);
    cudaGetSymbolAddress((void**)&lo,    g_lo);
    cudaGetSymbolAddress((void**)&mixb,  g_mixb);

    // ---- gate MLP ----
    tf32gemm_kernel<1, 0><<<dim3(GATE_H / 128, Bsz / 128), 256>>>(
        z, c, nullptr, gW[0], gbv[0], nullptr, h1, Bsz, GATE_H, INPUTD, 0);
    tf32gemm_kernel<0, 0><<<dim3(GATE_H / 128, Bsz / 128), 256>>>(
        h1, nullptr, nullptr, gW[1], gbv[1], nullptr, h2, Bsz, GATE_H, GATE_H, 0);
    gate2_kernel<<<(Bsz * 32 + 255) / 256, 256>>>(h2, gW[2], gbv[2], coeff);

    // ---- layer 0 ----
    ln_kernel<<<Bsz, 256>>>(z, c, COND, lng[0], lnb[0], xn, INPUTD);
    mixbias_kernel<<<(Bsz * HIDDEN + 255) / 256, 256>>>(coeff, bb[0], mixb, HIDDEN);
    tf32gemm_kernel<2, 1><<<dim3(HIDDEN / 128, Bsz / 128), 256>>>(
        xn, nullptr, coeff, w[0], mixb, nullptr, lo, Bsz, HIDDEN, NEXP * INPUTD, INPUTD);

    // ---- layers 1..3 (residual) ----
    for (int i = 1; i <= 3; i++) {
        ln_kernel<<<Bsz, 256>>>(z, lo, HIDDEN, lng[i], lnb[i], xn, INTERD);
        mixbias_kernel<<<(Bsz * HIDDEN + 255) / 256, 256>>>(coeff, bb[i], mixb, HIDDEN);
        tf32gemm_kernel<2, 2><<<dim3(HIDDEN / 128, Bsz / 128), 256>>>(
            xn, nullptr, coeff, w[i], mixb, lo, lo, Bsz, HIDDEN, NEXP * INTERD, INTERD);
    }

    // ---- final layer ----
    ln_kernel<<<Bsz, 256>>>(z, lo, HIDDEN, lng[4], lnb[4], xn, INTERD);
    mixbias_kernel<<<(Bsz * OUTD + 255) / 256, 256>>>(coeff, bb[4], mixb, OUTD);
    tf32gemm_kernel<2, 3><<<dim3(OUTD / 128, Bsz / 128), 256>>>(
        xn, nullptr, coeff, w[4], mixb, nullptr, (float*)d_out, Bsz, OUTD, NEXP * INTERD, INTERD);
}

// round 6
// speedup vs baseline: 3.3607x; 1.9604x over previous
#include <cuda_runtime.h>
#include <cuda_bf16.h>
#include <math.h>
#include <stdint.h>

// ---------------------------------------------------------------------------
// GatingMixedDecoder: gate MLP -> softmax coeff -> 5 soft-mixed expert layers.
// mix(coeff,x,w) folded into one GEMM with K = E*d1, A scaled by coeff[b,k/d1].
// tf32 mma.sync (legacy HMMA path; tcgen05 is unavailable: harness PTX targets
// plain sm_103, all tcgen05 a-features rejected by ptxas).
// BK=32, double-buffered smem, cp.async for B, pre-rounded tf32 weights.
// ---------------------------------------------------------------------------

#define Bsz    4096
#define LATENT 768
#define COND   512
#define HIDDEN 1024
#define OUTD   512
#define NEXP   8
#define GATE_H 512
#define INPUTD 1280   // LATENT+COND
#define INTERD 1792   // LATENT+HIDDEN
#define NEG_SLOPE 0.01f
#define LN_EPS 1e-5f

// ---- scratch (device globals; no allocation allowed) ----
__device__ float g_h1[Bsz * GATE_H];
__device__ float g_h2[Bsz * GATE_H];
__device__ float g_coeff[Bsz * NEXP];
__device__ float g_xn[Bsz * INTERD];
__device__ float g_lo[Bsz * HIDDEN];
__device__ float g_mixb[Bsz * HIDDEN];

// tf32-pre-rounded weights (same [K][N] layout as the inputs)
#define WT0_OFF   0ull                                   // [10240][1024]
#define WT1_OFF   (WT0_OFF + 10240ull * 1024ull)         // [14336][1024]
#define WT2_OFF   (WT1_OFF + 14336ull * 1024ull)
#define WT3_OFF   (WT2_OFF + 14336ull * 1024ull)
#define WT4_OFF   (WT3_OFF + 14336ull * 1024ull)         // [14336][512]
#define GWT0_OFF  (WT4_OFF + 14336ull * 512ull)          // [1280][512]
#define GWT1_OFF  (GWT0_OFF + 1280ull * 512ull)          // [512][512]
#define WT_TOTAL  (GWT1_OFF + 512ull * 512ull)
__device__ float g_wt[WT_TOTAL];

__device__ __forceinline__ unsigned f2tf32(float f) {
    unsigned u;
    asm("cvt.rna.tf32.f32 %0, %1;" : "=r"(u) : "f"(f));
    return u;
}
__device__ __forceinline__ float f2tf32f(float f) { return __uint_as_float(f2tf32(f)); }

__device__ __forceinline__ uint32_t smem_u32(const void* p) {
    uint32_t a;
    asm("{ .reg .u64 t; cvta.to.shared.u64 t, %1; cvt.u32.u64 %0, t; }" : "=r"(a) : "l"(p));
    return a;
}

// ---------------------------------------------------------------------------
// elementwise tf32 pre-round of weights
// ---------------------------------------------------------------------------
__global__ void __launch_bounds__(256)
roundcvt_kernel(const float* __restrict__ in, float* __restrict__ out, int n4)
{
    const int i = blockIdx.x * blockDim.x + threadIdx.x;
    if (i >= n4) return;
    float4 v = reinterpret_cast<const float4*>(in)[i];
    v.x = f2tf32f(v.x); v.y = f2tf32f(v.y); v.z = f2tf32f(v.z); v.w = f2tf32f(v.w);
    reinterpret_cast<float4*>(out)[i] = v;
}

// ---------------------------------------------------------------------------
// tf32 tensor-core GEMM: C[M,N] = A[M,K] @ B[K,N] (+ epilogue)
// BM=128 BN=128 BK=32, 256 threads (8 warps), warp tile 64x32 (m16n8k8).
// Double-buffered dynamic smem; B via cp.async (pre-rounded); A via registers.
// AMODE: 0 plain A1[M,K]; 1 concat(z[768], A2); 2 MoE coeff-scaled.
// EPI:   0 +bias[n],leaky; 1 +add[b,n],leaky; 2 +add[b,n]+resid,leaky; 3 +add[b,n].
// Requires M%128==0, N%128==0, K%32==0 (true at all call sites).
// ---------------------------------------------------------------------------
#define A_STRIDE 36                      // floats per A row (32 + 4 pad)
#define B_STRIDE 136                     // floats per B row (128 + 8 pad)
#define A_BYTES  (128 * A_STRIDE * 4)    // 18432
#define B_BYTES  (32 * B_STRIDE * 4)     // 17408
#define STAGE_BYTES (A_BYTES + B_BYTES)  // 35840
#define SMEM_TOTAL (2 * STAGE_BYTES)     // 71680

template <int AMODE, int EPI>
__global__ void __launch_bounds__(256)
tf32gemm_kernel(const float* __restrict__ A1, const float* __restrict__ A2,
                const float* __restrict__ coeff, const float* __restrict__ Bw,
                const float* __restrict__ addend, const float* __restrict__ resid,
                float* __restrict__ C, int M, int N, int K, int d1)
{
    extern __shared__ char smem[];
    const uint32_t smem_base = smem_u32(smem);

    const int tid  = threadIdx.x;
    const int warp = tid >> 5;
    const int lane = tid & 31;
    const int warp_m = (warp >> 2) * 64;
    const int warp_n = (warp & 3) * 32;
    const int grp = lane >> 2;     // 0..7
    const int tig = lane & 3;      // 0..3

    const int bm = blockIdx.y * 128;
    const int bn = blockIdx.x * 128;

    float acc[4][4][4];
#pragma unroll
    for (int i = 0; i < 4; i++)
#pragma unroll
        for (int j = 0; j < 4; j++)
#pragma unroll
            for (int r = 0; r < 4; r++) acc[i][j][r] = 0.f;

    float4 a_reg[4];

    // A tile: 128 rows x 32 cols = 1024 float4, 4/thread: row=idx>>3, c4=idx&7
#define LOADA(k0)                                                               \
    {                                                                           \
        _Pragma("unroll")                                                       \
        for (int i = 0; i < 4; i++) {                                           \
            const int idx = tid + i * 256;                                      \
            const int row = idx >> 3, c4 = idx & 7;                             \
            const int gm = bm + row, gk = (k0) + c4 * 4;                        \
            if (AMODE == 0) {                                                   \
                a_reg[i] = *reinterpret_cast<const float4*>(A1 + (size_t)gm * K + gk); \
            } else if (AMODE == 1) {                                            \
                if (gk < LATENT)                                                \
                    a_reg[i] = *reinterpret_cast<const float4*>(A1 + (size_t)gm * LATENT + gk); \
                else                                                            \
                    a_reg[i] = *reinterpret_cast<const float4*>(A2 + (size_t)gm * (K - LATENT) + (gk - LATENT)); \
            } else {                                                            \
                const int e = gk / d1;                                          \
                const int j = gk - e * d1;                                      \
                const float cf = __ldg(coeff + gm * NEXP + e);                  \
                float4 x = *reinterpret_cast<const float4*>(A1 + (size_t)gm * d1 + j); \
                a_reg[i] = make_float4(x.x * cf, x.y * cf, x.z * cf, x.w * cf); \
            }                                                                   \
        }                                                                       \
    }

#define STOREA(s)                                                               \
    {                                                                           \
        float* Af = reinterpret_cast<float*>(smem + (s) * STAGE_BYTES);         \
        _Pragma("unroll")                                                       \
        for (int i = 0; i < 4; i++) {                                           \
            const int idx = tid + i * 256;                                      \
            const int row = idx >> 3, c4 = idx & 7;                             \
            float4 v = a_reg[i];                                                \
            v.x = f2tf32f(v.x); v.y = f2tf32f(v.y);                             \
            v.z = f2tf32f(v.z); v.w = f2tf32f(v.w);                             \
            *reinterpret_cast<float4*>(Af + row * A_STRIDE + c4 * 4) = v;       \
        }                                                                       \
    }

    // B tile: 32 rows x 128 cols = 1024 float4, 4/thread: row=idx>>5, c4=idx&31
#define CPB(s, k0)                                                              \
    {                                                                           \
        const uint32_t bbase = smem_base + (s) * STAGE_BYTES + A_BYTES;         \
        _Pragma("unroll")                                                       \
        for (int i = 0; i < 4; i++) {                                           \
            const int idx = tid + i * 256;                                      \
            const int row = idx >> 5, c4 = idx & 31;                            \
            const uint32_t dst = bbase + (uint32_t)(row * B_STRIDE + c4 * 4) * 4; \
            const float* src = Bw + (size_t)((k0) + row) * N + bn + c4 * 4;     \
            asm volatile("cp.async.cg.shared.global [%0], [%1], 16;"            \
                         :: "r"(dst), "l"(src));                                \
        }                                                                       \
        asm volatile("cp.async.commit_group;");                                 \
    }

    const int nt = K >> 5;

    // prologue: fill stage 0
    LOADA(0);
    CPB(0, 0);
    STOREA(0);
    asm volatile("cp.async.wait_group 0;");
    __syncthreads();

    for (int kt = 0; kt < nt; kt++) {
        const int s = kt & 1;
        if (kt + 1 < nt) {
            LOADA((kt + 1) << 5);
            CPB(s ^ 1, (kt + 1) << 5);
        }

        const float* Af = reinterpret_cast<const float*>(smem + s * STAGE_BYTES);
        const float* Bf = reinterpret_cast<const float*>(smem + s * STAGE_BYTES + A_BYTES);

#pragma unroll
        for (int ks = 0; ks < 4; ks++) {
            const int kk = ks * 8;
            unsigned bfr[4][2];
#pragma unroll
            for (int ntt = 0; ntt < 4; ntt++) {
                const int n = warp_n + ntt * 8 + grp;
                bfr[ntt][0] = __float_as_uint(Bf[(kk + tig) * B_STRIDE + n]);
                bfr[ntt][1] = __float_as_uint(Bf[(kk + 4 + tig) * B_STRIDE + n]);
            }
            unsigned afr[4][4];
#pragma unroll
            for (int mt = 0; mt < 4; mt++) {
                const int m = warp_m + mt * 16 + grp;
                afr[mt][0] = __float_as_uint(Af[m * A_STRIDE + kk + tig]);
                afr[mt][1] = __float_as_uint(Af[(m + 8) * A_STRIDE + kk + tig]);
                afr[mt][2] = __float_as_uint(Af[m * A_STRIDE + kk + 4 + tig]);
                afr[mt][3] = __float_as_uint(Af[(m + 8) * A_STRIDE + kk + 4 + tig]);
            }
#pragma unroll
            for (int mt = 0; mt < 4; mt++)
#pragma unroll
                for (int ntt = 0; ntt < 4; ntt++) {
                    asm volatile(
                        "mma.sync.aligned.m16n8k8.row.col.f32.tf32.tf32.f32 "
                        "{%0,%1,%2,%3}, {%4,%5,%6,%7}, {%8,%9}, {%0,%1,%2,%3};"
                        : "+f"(acc[mt][ntt][0]), "+f"(acc[mt][ntt][1]),
                          "+f"(acc[mt][ntt][2]), "+f"(acc[mt][ntt][3])
                        : "r"(afr[mt][0]), "r"(afr[mt][1]),
                          "r"(afr[mt][2]), "r"(afr[mt][3]),
                          "r"(bfr[ntt][0]), "r"(bfr[ntt][1]));
                }
        }

        if (kt + 1 < nt) STOREA(s ^ 1);
        asm volatile("cp.async.wait_group 0;");
        __syncthreads();
    }

    // ---- epilogue: c0,c1 at (row, col..col+1); c2,c3 at (row+8, ...) ----
#pragma unroll
    for (int mt = 0; mt < 4; mt++) {
        const int r0 = bm + warp_m + mt * 16 + grp;
#pragma unroll
        for (int ntt = 0; ntt < 4; ntt++) {
            const int c0 = bn + warp_n + ntt * 8 + tig * 2;
#pragma unroll
            for (int half = 0; half < 2; half++) {
                const int gr = r0 + half * 8;
                float v0 = acc[mt][ntt][half * 2 + 0];
                float v1 = acc[mt][ntt][half * 2 + 1];
                if (EPI == 0) {
                    const float2 ad = *reinterpret_cast<const float2*>(addend + c0);
                    v0 += ad.x; v1 += ad.y;
                } else {
                    const float2 ad = *reinterpret_cast<const float2*>(addend + (size_t)gr * N + c0);
                    v0 += ad.x; v1 += ad.y;
                }
                if (EPI == 2) {
                    const float2 rs = *reinterpret_cast<const float2*>(resid + (size_t)gr * N + c0);
                    v0 += rs.x; v1 += rs.y;
                }
                if (EPI != 3) {
                    v0 = (v0 > 0.f) ? v0 : NEG_SLOPE * v0;
                    v1 = (v1 > 0.f) ? v1 : NEG_SLOPE * v1;
                }
                *reinterpret_cast<float2*>(C + (size_t)gr * N + c0) = make_float2(v0, v1);
            }
        }
    }
#undef LOADA
#undef STOREA
#undef CPB
}

// ---------------------------------------------------------------------------
// LayerNorm over concat(z[768], src[srclen]); single pass, warp-shuffle reduce.
// ---------------------------------------------------------------------------
__global__ void __launch_bounds__(256)
ln_kernel(const float* __restrict__ z, const float* __restrict__ src, int srclen,
          const float* __restrict__ g, const float* __restrict__ b,
          float* __restrict__ out, int d)
{
    const int row = blockIdx.x;
    __shared__ float buf[INTERD];
    __shared__ float ws[8], wq[8];
    __shared__ float mu_s, rstd_s;
    const int tid = threadIdx.x, wid = tid >> 5, lane = tid & 31;

    float s = 0.f, sq = 0.f;
    for (int j = tid; j < d; j += 256) {
        float v = (j < LATENT) ? z[(size_t)row * LATENT + j]
                               : src[(size_t)row * srclen + (j - LATENT)];
        buf[j] = v;
        s += v; sq = fmaf(v, v, sq);
    }
#pragma unroll
    for (int o = 16; o > 0; o >>= 1) {
        s  += __shfl_down_sync(0xffffffffu, s, o);
        sq += __shfl_down_sync(0xffffffffu, sq, o);
    }
    if (lane == 0) { ws[wid] = s; wq[wid] = sq; }
    __syncthreads();
    if (tid == 0) {
        float S = 0.f, Q = 0.f;
#pragma unroll
        for (int i = 0; i < 8; i++) { S += ws[i]; Q += wq[i]; }
        const float mu = S / d;
        mu_s = mu;
        rstd_s = rsqrtf(Q / d - mu * mu + LN_EPS);
    }
    __syncthreads();
    const float mu = mu_s, rstd = rstd_s;
    for (int j = tid; j < d; j += 256)
        out[(size_t)row * d + j] = (buf[j] - mu) * rstd * g[j] + b[j];
}

// ---------------------------------------------------------------------------
// gate layer 3 + softmax (one warp per row)
// ---------------------------------------------------------------------------
__global__ void __launch_bounds__(256)
gate2_kernel(const float* __restrict__ h, const float* __restrict__ W,
             const float* __restrict__ bias, float* __restrict__ coeff)
{
    const int warp = (blockIdx.x * blockDim.x + threadIdx.x) >> 5;
    const int lane = threadIdx.x & 31;
    if (warp >= Bsz) return;

    float acc[NEXP];
#pragma unroll
    for (int e = 0; e < NEXP; e++) acc[e] = 0.f;
    for (int j = lane; j < GATE_H; j += 32) {
        const float hv = h[(size_t)warp * GATE_H + j];
        const float4 w0 = *reinterpret_cast<const float4*>(W + (size_t)j * NEXP);
        const float4 w1 = *reinterpret_cast<const float4*>(W + (size_t)j * NEXP + 4);
        acc[0] = fmaf(hv, w0.x, acc[0]); acc[1] = fmaf(hv, w0.y, acc[1]);
        acc[2] = fmaf(hv, w0.z, acc[2]); acc[3] = fmaf(hv, w0.w, acc[3]);
        acc[4] = fmaf(hv, w1.x, acc[4]); acc[5] = fmaf(hv, w1.y, acc[5]);
        acc[6] = fmaf(hv, w1.z, acc[6]); acc[7] = fmaf(hv, w1.w, acc[7]);
    }
#pragma unroll
    for (int e = 0; e < NEXP; e++)
#pragma unroll
        for (int o = 16; o > 0; o >>= 1)
            acc[e] += __shfl_down_sync(0xffffffffu, acc[e], o);
    if (lane == 0) {
        float v[NEXP], m = -1e30f;
#pragma unroll
        for (int e = 0; e < NEXP; e++) { v[e] = acc[e] + bias[e]; m = fmaxf(m, v[e]); }
        float sum = 0.f;
#pragma unroll
        for (int e = 0; e < NEXP; e++) { v[e] = __expf(v[e] - m); sum += v[e]; }
        const float inv = 1.f / sum;
#pragma unroll
        for (int e = 0; e < NEXP; e++) coeff[(size_t)warp * NEXP + e] = v[e] * inv;
    }
}

// ---------------------------------------------------------------------------
// mixed bias: mixb[b,n] = sum_e coeff[b,e] * bias[e,n]
// ---------------------------------------------------------------------------
__global__ void __launch_bounds__(256)
mixbias_kernel(const float* __restrict__ coeff, const float* __restrict__ bias,
               float* __restrict__ out, int N)
{
    const int idx = blockIdx.x * blockDim.x + threadIdx.x;
    if (idx >= Bsz * N) return;
    const int b = idx / N, n = idx - b * N;
    const float* cf = coeff + (size_t)b * NEXP;
    float s = 0.f;
#pragma unroll
    for (int e = 0; e < NEXP; e++) s = fmaf(cf[e], bias[(size_t)e * N + n], s);
    out[idx] = s;
}

// ---------------------------------------------------------------------------
extern "C" void kernel_launch(void* const* d_in, const int* in_sizes, int n_in,
                              void* d_out, int out_size)
{
    const float* z = (const float*)d_in[0];
    const float* c = (const float*)d_in[1];
    const float *w[5], *bb[5], *lng[5], *lnb[5], *gW[3], *gbv[3];

    const bool dict_order = (in_sizes[4] == INPUTD);
    if (dict_order) {
        for (int i = 0; i < 5; i++) {
            w[i]   = (const float*)d_in[2 + 4 * i];
            bb[i]  = (const float*)d_in[3 + 4 * i];
            lng[i] = (const float*)d_in[4 + 4 * i];
            lnb[i] = (const float*)d_in[5 + 4 * i];
        }
    } else {
        for (int i = 0; i < 5; i++) {
            w[i]   = (const float*)d_in[2 + 2 * i];
            bb[i]  = (const float*)d_in[3 + 2 * i];
            lng[i] = (const float*)d_in[12 + 2 * i];
            lnb[i] = (const float*)d_in[13 + 2 * i];
        }
    }
    for (int j = 0; j < 3; j++) {
        gW[j]  = (const float*)d_in[22 + 2 * j];
        gbv[j] = (const float*)d_in[23 + 2 * j];
    }

    float *h1, *h2, *coeff, *xn, *lo, *mixb, *wt;
    cudaGetSymbolAddress((void**)&h1,    g_h1);
    cudaGetSymbolAddress((void**)&h2,    g_h2);
    cudaGetSymbolAddress((void**)&coeff, g_coeff);
    cudaGetSymbolAddress((void**)&xn,    g_xn);
    cudaGetSymbolAddress((void**)&lo,    g_lo);
    cudaGetSymbolAddress((void**)&mixb,  g_mixb);
    cudaGetSymbolAddress((void**)&wt,    g_wt);

    // dynamic smem opt-in (idempotent host attribute; capture-safe)
    cudaFuncSetAttribute(tf32gemm_kernel<1, 0>, cudaFuncAttributeMaxDynamicSharedMemorySize, SMEM_TOTAL);
    cudaFuncSetAttribute(tf32gemm_kernel<0, 0>, cudaFuncAttributeMaxDynamicSharedMemorySize, SMEM_TOTAL);
    cudaFuncSetAttribute(tf32gemm_kernel<2, 1>, cudaFuncAttributeMaxDynamicSharedMemorySize, SMEM_TOTAL);
    cudaFuncSetAttribute(tf32gemm_kernel<2, 2>, cudaFuncAttributeMaxDynamicSharedMemorySize, SMEM_TOTAL);
    cudaFuncSetAttribute(tf32gemm_kernel<2, 3>, cudaFuncAttributeMaxDynamicSharedMemorySize, SMEM_TOTAL);

    // ---- pre-round weights to tf32 (elementwise) ----
    {
        const struct { const float* src; uint64_t off; uint64_t n; } cv[7] = {
            { w[0],  WT0_OFF,  10240ull * 1024ull },
            { w[1],  WT1_OFF,  14336ull * 1024ull },
            { w[2],  WT2_OFF,  14336ull * 1024ull },
            { w[3],  WT3_OFF,  14336ull * 1024ull },
            { w[4],  WT4_OFF,  14336ull * 512ull  },
            { gW[0], GWT0_OFF, 1280ull * 512ull   },
            { gW[1], GWT1_OFF, 512ull * 512ull    },
        };
        for (int i = 0; i < 7; i++) {
            const int n4 = (int)(cv[i].n / 4);
            roundcvt_kernel<<<(n4 + 255) / 256, 256>>>(cv[i].src, wt + cv[i].off, n4);
        }
    }

    // ---- gate MLP ----
    tf32gemm_kernel<1, 0><<<dim3(GATE_H / 128, Bsz / 128), 256, SMEM_TOTAL>>>(
        z, c, nullptr, wt + GWT0_OFF, gbv[0], nullptr, h1, Bsz, GATE_H, INPUTD, 0);
    tf32gemm_kernel<0, 0><<<dim3(GATE_H / 128, Bsz / 128), 256, SMEM_TOTAL>>>(
        h1, nullptr, nullptr, wt + GWT1_OFF, gbv[1], nullptr, h2, Bsz, GATE_H, GATE_H, 0);
    gate2_kernel<<<(Bsz * 32 + 255) / 256, 256>>>(h2, gW[2], gbv[2], coeff);

    // ---- layer 0 ----
    ln_kernel<<<Bsz, 256>>>(z, c, COND, lng[0], lnb[0], xn, INPUTD);
    mixbias_kernel<<<(Bsz * HIDDEN + 255) / 256, 256>>>(coeff, bb[0], mixb, HIDDEN);
    tf32gemm_kernel<2, 1><<<dim3(HIDDEN / 128, Bsz / 128), 256, SMEM_TOTAL>>>(
        xn, nullptr, coeff, wt + WT0_OFF, mixb, nullptr, lo, Bsz, HIDDEN, NEXP * INPUTD, INPUTD);

    // ---- layers 1..3 (residual) ----
    const uint64_t wtoff[3] = { WT1_OFF, WT2_OFF, WT3_OFF };
    for (int i = 1; i <= 3; i++) {
        ln_kernel<<<Bsz, 256>>>(z, lo, HIDDEN, lng[i], lnb[i], xn, INTERD);
        mixbias_kernel<<<(Bsz * HIDDEN + 255) / 256, 256>>>(coeff, bb[i], mixb, HIDDEN);
        tf32gemm_kernel<2, 2><<<dim3(HIDDEN / 128, Bsz / 128), 256, SMEM_TOTAL>>>(
            xn, nullptr, coeff, wt + wtoff[i - 1], mixb, lo, lo, Bsz, HIDDEN, NEXP * INTERD, INTERD);
    }

    // ---- final layer ----
    ln_kernel<<<Bsz, 256>>>(z, lo, HIDDEN, lng[4], lnb[4], xn, INTERD);
    mixbias_kernel<<<(Bsz * OUTD + 255) / 256, 256>>>(coeff, bb[4], mixb, OUTD);
    tf32gemm_kernel<2, 3><<<dim3(OUTD / 128, Bsz / 128), 256, SMEM_TOTAL>>>(
        xn, nullptr, coeff, wt + WT4_OFF, mixb, nullptr, (float*)d_out, Bsz, OUTD, NEXP * INTERD, INTERD);
}